// round 5
// baseline (speedup 1.0000x reference)
#include <cuda_runtime.h>
#include <math.h>

#define N_NODES_MAX 100000
#define N_EDGES_MAX 3200000

// Scratch (device globals: no allocation in kernel_launch)
__device__ __align__(128) float  g_deg[N_NODES_MAX];         // deg accum, then dis (in place)
__device__ __align__(128) float  g_w2[N_NODES_MAX];          // sum over out-edges of ewc*dis[dst]
__device__ __align__(128) float4 g_xs4[N_NODES_MAX];         // (x0..x3)*dis, 16B/node
__device__ __align__(128) float  g_x4[N_NODES_MAX];          // x4*dis (separate small array)
__device__ __align__(128) float4 g_aggx[N_NODES_MAX * 2];    // 5-dim accumulator (unscaled by dis[dst])
__device__ __align__(128) float  g_ewc[N_EDGES_MAX];         // compact edge weight
__device__ float g_acc[16];                                  // final 16-vec reduction

__device__ __forceinline__ void red4(float4* p, float a, float b, float c, float d) {
    asm volatile("red.global.add.v4.f32 [%0], {%1,%2,%3,%4};"
                 :: "l"(p), "f"(a), "f"(b), "f"(c), "f"(d) : "memory");
}
__device__ __forceinline__ void red1(float* p, float a) {
    asm volatile("red.global.add.f32 [%0], %1;" :: "l"(p), "f"(a) : "memory");
}

// ---------------------------------------------------------------------------
// Pass 1: zero deg only (rest is zeroed in k_dis)
// ---------------------------------------------------------------------------
__global__ void k_zero_deg(int N) {
    int i = blockIdx.x * blockDim.x + threadIdx.x;
    if (i < N) g_deg[i] = 0.f;
}

// ---------------------------------------------------------------------------
// Pass 2: deg[dst] += ew; compact edge weights
// ---------------------------------------------------------------------------
__global__ void k_deg(const int* __restrict__ ei, const float* __restrict__ ea, int E) {
    int e = blockIdx.x * blockDim.x + threadIdx.x;
    if (e >= E) return;
    int d = ei[E + e];
    float w = ea[(size_t)4 * e];
    g_ewc[e] = w;
    red1(&g_deg[d], w);
}

// ---------------------------------------------------------------------------
// Pass 3: dis = rsqrt(1 + deg); xs4 = (x0..x3)*dis; x4s = x4*dis;
//         zero aggx, w2, acc
// ---------------------------------------------------------------------------
__global__ void k_dis(const float* __restrict__ x, int N) {
    int i = blockIdx.x * blockDim.x + threadIdx.x;
    if (blockIdx.x == 0 && threadIdx.x < 16) g_acc[threadIdx.x] = 0.f;
    if (i >= N) return;
    float di = rsqrtf(1.0f + g_deg[i]);
    g_deg[i] = di;
    float x0 = x[i * 5 + 0], x1 = x[i * 5 + 1], x2 = x[i * 5 + 2];
    float x3 = x[i * 5 + 3], x4 = x[i * 5 + 4];
    g_xs4[i] = make_float4(x0 * di, x1 * di, x2 * di, x3 * di);
    g_x4[i] = x4 * di;
    g_w2[i] = 0.f;
    float4 z = make_float4(0.f, 0.f, 0.f, 0.f);
    g_aggx[i * 2] = z;
    g_aggx[i * 2 + 1] = z;
}

// ---------------------------------------------------------------------------
// Pass 4: per edge:
//   aggx[dst] += xs[src] * ewc          (dis[dst] factored out, applied later)
//   w2[src]   += ewc * dis[dst]
// ---------------------------------------------------------------------------
__global__ void k_agg1(const int* __restrict__ ei, int E) {
    int e = blockIdx.x * blockDim.x + threadIdx.x;
    if (e >= E) return;
    int s = ei[e];
    int d = ei[E + e];
    float w = g_ewc[e];
    float4 m = g_xs4[s];
    float  m4 = g_x4[s];
    float  dd = g_deg[d];
    float4* op = &g_aggx[(size_t)d * 2];
    red4(op, m.x * w, m.y * w, m.z * w, m.w * w);
    red1((float*)(op + 1), m4 * w);
    red1(&g_w2[s], w * dd);
}

// ---------------------------------------------------------------------------
// Pass 5: per node:
//   a5 = dis * (aggR + xs)   (includes self-loop);  h = relu(a5 @ W1 + b1)
//   acc += h * (dis*w2 + dis^2)
// ---------------------------------------------------------------------------
__global__ void k_post(const float* __restrict__ W1, const float* __restrict__ b1, int N) {
    __shared__ float sW[80];
    __shared__ float sB[16];
    if (threadIdx.x < 80) sW[threadIdx.x] = W1[threadIdx.x];
    if (threadIdx.x < 16) sB[threadIdx.x] = b1[threadIdx.x];
    __syncthreads();
    int i = blockIdx.x * blockDim.x + threadIdx.x;
    float v[16];
#pragma unroll
    for (int c = 0; c < 16; c++) v[c] = 0.f;
    if (i < N) {
        float di = g_deg[i];
        float d2 = di * di;
        float coef = fmaf(di, g_w2[i], d2);
        float4 a0 = g_aggx[i * 2];
        float  a4 = ((const float*)&g_aggx[i * 2 + 1])[0];
        float4 xs = g_xs4[i];
        float  x4 = g_x4[i];
        float a5[5];
        a5[0] = di * (a0.x + xs.x);
        a5[1] = di * (a0.y + xs.y);
        a5[2] = di * (a0.z + xs.z);
        a5[3] = di * (a0.w + xs.w);
        a5[4] = di * (a4 + x4);
#pragma unroll
        for (int c = 0; c < 16; c++) {
            float h = sB[c];
#pragma unroll
            for (int k = 0; k < 5; k++) h = fmaf(a5[k], sW[k * 16 + c], h);
            v[c] = fmaxf(h, 0.f) * coef;
        }
    }
    // warp -> block -> global reduction
#pragma unroll
    for (int c = 0; c < 16; c++)
#pragma unroll
        for (int m = 16; m > 0; m >>= 1) v[c] += __shfl_xor_sync(0xffffffffu, v[c], m);
    __shared__ float sb[16];
    if (threadIdx.x < 16) sb[threadIdx.x] = 0.f;
    __syncthreads();
    if ((threadIdx.x & 31) == 0) {
#pragma unroll
        for (int c = 0; c < 16; c++) atomicAdd(&sb[c], v[c]);
    }
    __syncthreads();
    if (threadIdx.x < 16) atomicAdd(&g_acc[threadIdx.x], sb[threadIdx.x]);
}

// ---------------------------------------------------------------------------
// Pass 6: state = (g_acc/N)@W2 + b2; MLP 4->128->64->50; softmax
// ---------------------------------------------------------------------------
__global__ void k_final(const float* __restrict__ W2, const float* __restrict__ b2,
                        const float* __restrict__ pW1, const float* __restrict__ pb1,
                        const float* __restrict__ pW2, const float* __restrict__ pb2,
                        const float* __restrict__ pW3, const float* __restrict__ pb3,
                        float* __restrict__ out, int N) {
    __shared__ float st[4];
    __shared__ float z1[128];
    __shared__ float z2[64];
    __shared__ float lg[50];
    __shared__ float ms[2];
    int t = threadIdx.x;
    if (t < 4) {
        float s = 0.f;
#pragma unroll
        for (int k = 0; k < 16; k++) s = fmaf(g_acc[k], W2[k * 4 + t], s);
        st[t] = s / (float)N + b2[t];
    }
    __syncthreads();
    {
        float vv = pb1[t];
#pragma unroll
        for (int j = 0; j < 4; j++) vv = fmaf(st[j], pW1[j * 128 + t], vv);
        z1[t] = fmaxf(vv, 0.f);
    }
    __syncthreads();
    if (t < 64) {
        float vv = pb2[t];
#pragma unroll 8
        for (int k = 0; k < 128; k++) vv = fmaf(z1[k], pW2[k * 64 + t], vv);
        z2[t] = fmaxf(vv, 0.f);
    }
    __syncthreads();
    if (t < 50) {
        float vv = pb3[t];
#pragma unroll 8
        for (int k = 0; k < 64; k++) vv = fmaf(z2[k], pW3[k * 50 + t], vv);
        lg[t] = vv;
    }
    __syncthreads();
    if (t == 0) {
        float m = lg[0];
        for (int k = 1; k < 50; k++) m = fmaxf(m, lg[k]);
        float s = 0.f;
        for (int k = 0; k < 50; k++) s += expf(lg[k] - m);
        ms[0] = m;
        ms[1] = s;
    }
    __syncthreads();
    if (t < 50) out[t] = expf(lg[t] - ms[0]) / ms[1];
}

// ---------------------------------------------------------------------------
extern "C" void kernel_launch(void* const* d_in, const int* in_sizes, int n_in,
                              void* d_out, int out_size) {
    const float* x   = (const float*)d_in[0];
    const int*   ei  = (const int*)  d_in[1];
    const float* ea  = (const float*)d_in[2];
    const float* W1  = (const float*)d_in[3];
    const float* b1  = (const float*)d_in[4];
    const float* W2  = (const float*)d_in[5];
    const float* b2  = (const float*)d_in[6];
    const float* pW1 = (const float*)d_in[7];
    const float* pb1 = (const float*)d_in[8];
    const float* pW2 = (const float*)d_in[9];
    const float* pb2 = (const float*)d_in[10];
    const float* pW3 = (const float*)d_in[11];
    const float* pb3 = (const float*)d_in[12];
    float* out = (float*)d_out;

    int N = in_sizes[0] / 5;
    int E = in_sizes[1] / 2;
    const int TB = 256;
    int nb = (N + TB - 1) / TB;
    int eb = (E + TB - 1) / TB;

    k_zero_deg<<<nb, TB>>>(N);
    k_deg<<<eb, TB>>>(ei, ea, E);
    k_dis<<<nb, TB>>>(x, N);
    k_agg1<<<eb, TB>>>(ei, E);
    k_post<<<nb, TB>>>(W1, b1, N);
    k_final<<<1, 128>>>(W2, b2, pW1, pb1, pW2, pb2, pW3, pb3, out, N);
}

// round 6
// speedup vs baseline: 1.0403x; 1.0403x over previous
#include <cuda_runtime.h>
#include <math.h>

#define N_NODES_MAX 100000
#define N_EDGES_MAX 3200000

// Scratch (device globals: no allocation in kernel_launch)
__device__ __align__(128) float  g_deg[N_NODES_MAX];         // deg accum, then dis (in place)
__device__ __align__(128) float  g_w2[N_NODES_MAX];          // sum over out-edges of ewc*dis[dst]
__device__ __align__(128) float4 g_xs[N_NODES_MAX * 2];      // x*dis padded to 32B/node
__device__ __align__(128) float4 g_aggx[N_NODES_MAX * 2];    // 5-dim edge accumulator, 32B/node
__device__ __align__(128) float  g_ewc[N_EDGES_MAX];         // compact edge weight
__device__ float g_acc[16];                                  // final 16-vec reduction
__device__ unsigned int g_done;                              // k_post completion counter

__device__ __forceinline__ void red4(float4* p, float a, float b, float c, float d) {
    asm volatile("red.global.add.v4.f32 [%0], {%1,%2,%3,%4};"
                 :: "l"(p), "f"(a), "f"(b), "f"(c), "f"(d) : "memory");
}
__device__ __forceinline__ void red1(float* p, float a) {
    asm volatile("red.global.add.f32 [%0], %1;" :: "l"(p), "f"(a) : "memory");
}

// ---------------------------------------------------------------------------
// Pass 1: zero deg, w2, aggx, acc, done-counter
// ---------------------------------------------------------------------------
__global__ void k_zero(int N) {
    int i = blockIdx.x * blockDim.x + threadIdx.x;
    if (blockIdx.x == 0 && threadIdx.x < 16) g_acc[threadIdx.x] = 0.f;
    if (blockIdx.x == 0 && threadIdx.x == 0) g_done = 0u;
    if (i >= N) return;
    g_deg[i] = 0.f;
    g_w2[i] = 0.f;
    float4 z = make_float4(0.f, 0.f, 0.f, 0.f);
    g_aggx[i * 2] = z;
    g_aggx[i * 2 + 1] = z;
}

// ---------------------------------------------------------------------------
// Pass 2: deg[dst] += ew; compact edge weights (vectorized ea read)
// ---------------------------------------------------------------------------
__global__ void k_deg(const int* __restrict__ ei, const float4* __restrict__ ea4, int E) {
    int e = blockIdx.x * blockDim.x + threadIdx.x;
    if (e >= E) return;
    int d = ei[E + e];
    float w = ea4[e].x;
    g_ewc[e] = w;
    red1(&g_deg[d], w);
}

// ---------------------------------------------------------------------------
// Pass 3: dis = rsqrt(1 + deg); xs = x * dis (padded to 8 floats)
// ---------------------------------------------------------------------------
__global__ void k_dis(const float* __restrict__ x, int N) {
    int i = blockIdx.x * blockDim.x + threadIdx.x;
    if (i >= N) return;
    float di = rsqrtf(1.0f + g_deg[i]);
    g_deg[i] = di;
    float x0 = x[i * 5 + 0], x1 = x[i * 5 + 1], x2 = x[i * 5 + 2];
    float x3 = x[i * 5 + 3], x4 = x[i * 5 + 4];
    g_xs[i * 2]     = make_float4(x0 * di, x1 * di, x2 * di, x3 * di);
    g_xs[i * 2 + 1] = make_float4(x4 * di, 0.f, 0.f, 0.f);
}

// ---------------------------------------------------------------------------
// Pass 4: per edge: c = ewc * dis[dst]
//   aggx[dst] += xs[src] * c   (5 floats: red.v4 + red1, one 32B sector)
//   w2[src]   += c
// ---------------------------------------------------------------------------
__global__ void k_agg1(const int* __restrict__ ei, int E) {
    int e = blockIdx.x * blockDim.x + threadIdx.x;
    if (e >= E) return;
    int s = ei[e];
    int d = ei[E + e];
    float c = g_ewc[e] * g_deg[d];
    float4 m0 = g_xs[(size_t)s * 2];
    float  m4 = ((const float*)&g_xs[(size_t)s * 2 + 1])[0];
    float4* op = &g_aggx[(size_t)d * 2];
    red4(op, m0.x * c, m0.y * c, m0.z * c, m0.w * c);
    red1((float*)(op + 1), m4 * c);
    red1(&g_w2[s], c);
}

// ---------------------------------------------------------------------------
// Pass 5 (fused): per node:
//   a5 = aggx + xs*dis (self loop);  h = relu(a5 @ W1 + b1)  (5 -> 16)
//   acc += h * (dis*w2 + dis^2)
// Last block then runs: state = (acc/N)@W2 + b2; MLP 4->128->64->50; softmax
// ---------------------------------------------------------------------------
__global__ void k_post(const float* __restrict__ W1, const float* __restrict__ b1,
                       const float* __restrict__ W2, const float* __restrict__ b2,
                       const float* __restrict__ pW1, const float* __restrict__ pb1,
                       const float* __restrict__ pW2, const float* __restrict__ pb2,
                       const float* __restrict__ pW3, const float* __restrict__ pb3,
                       float* __restrict__ out, int N) {
    __shared__ float sW[80];
    __shared__ float sB[16];
    if (threadIdx.x < 80) sW[threadIdx.x] = W1[threadIdx.x];
    if (threadIdx.x < 16) sB[threadIdx.x] = b1[threadIdx.x];
    __syncthreads();
    int i = blockIdx.x * blockDim.x + threadIdx.x;
    float v[16];
#pragma unroll
    for (int c = 0; c < 16; c++) v[c] = 0.f;
    if (i < N) {
        float di = g_deg[i];
        float coef = fmaf(di, g_w2[i], di * di);
        float4 a0 = g_aggx[i * 2];
        float  a4 = ((const float*)&g_aggx[i * 2 + 1])[0];
        float4 xs = g_xs[i * 2];
        float  x4 = ((const float*)&g_xs[i * 2 + 1])[0];
        float a5[5];
        a5[0] = fmaf(xs.x, di, a0.x);
        a5[1] = fmaf(xs.y, di, a0.y);
        a5[2] = fmaf(xs.z, di, a0.z);
        a5[3] = fmaf(xs.w, di, a0.w);
        a5[4] = fmaf(x4,   di, a4);
#pragma unroll
        for (int c = 0; c < 16; c++) {
            float h = sB[c];
#pragma unroll
            for (int k = 0; k < 5; k++) h = fmaf(a5[k], sW[k * 16 + c], h);
            v[c] = fmaxf(h, 0.f) * coef;
        }
    }
    // warp -> block -> global reduction
#pragma unroll
    for (int c = 0; c < 16; c++)
#pragma unroll
        for (int m = 16; m > 0; m >>= 1) v[c] += __shfl_xor_sync(0xffffffffu, v[c], m);
    __shared__ float sb[16];
    if (threadIdx.x < 16) sb[threadIdx.x] = 0.f;
    __syncthreads();
    if ((threadIdx.x & 31) == 0) {
#pragma unroll
        for (int c = 0; c < 16; c++) atomicAdd(&sb[c], v[c]);
    }
    __syncthreads();
    if (threadIdx.x < 16) atomicAdd(&g_acc[threadIdx.x], sb[threadIdx.x]);

    // ---- last-block-done: run the tiny MLP head ----
    __shared__ bool isLast;
    __threadfence();
    if (threadIdx.x == 0) {
        unsigned int ticket = atomicAdd(&g_done, 1u);
        isLast = (ticket == gridDim.x - 1);
    }
    __syncthreads();
    if (!isLast) return;
    if (threadIdx.x == 0) g_done = 0u;   // reset for next graph replay

    __shared__ float st[4];
    __shared__ float z1[128];
    __shared__ float z2[64];
    __shared__ float lg[50];
    __shared__ float ms[2];
    int t = threadIdx.x;
    if (t < 4) {
        float s = 0.f;
#pragma unroll
        for (int k = 0; k < 16; k++) {
            float av;
            asm volatile("ld.volatile.global.f32 %0, [%1];" : "=f"(av) : "l"(&g_acc[k]));
            s = fmaf(av, W2[k * 4 + t], s);
        }
        st[t] = s / (float)N + b2[t];
    }
    __syncthreads();
    if (t < 128) {
        float vv = pb1[t];
#pragma unroll
        for (int j = 0; j < 4; j++) vv = fmaf(st[j], pW1[j * 128 + t], vv);
        z1[t] = fmaxf(vv, 0.f);
    }
    __syncthreads();
    if (t < 64) {
        float vv = pb2[t];
#pragma unroll 8
        for (int k = 0; k < 128; k++) vv = fmaf(z1[k], pW2[k * 64 + t], vv);
        z2[t] = fmaxf(vv, 0.f);
    }
    __syncthreads();
    if (t < 50) {
        float vv = pb3[t];
#pragma unroll 8
        for (int k = 0; k < 64; k++) vv = fmaf(z2[k], pW3[k * 50 + t], vv);
        lg[t] = vv;
    }
    __syncthreads();
    if (t == 0) {
        float m = lg[0];
        for (int k = 1; k < 50; k++) m = fmaxf(m, lg[k]);
        float s = 0.f;
        for (int k = 0; k < 50; k++) s += expf(lg[k] - m);
        ms[0] = m;
        ms[1] = s;
    }
    __syncthreads();
    if (t < 50) out[t] = expf(lg[t] - ms[0]) / ms[1];
}

// ---------------------------------------------------------------------------
extern "C" void kernel_launch(void* const* d_in, const int* in_sizes, int n_in,
                              void* d_out, int out_size) {
    const float* x   = (const float*)d_in[0];
    const int*   ei  = (const int*)  d_in[1];
    const float* ea  = (const float*)d_in[2];
    const float* W1  = (const float*)d_in[3];
    const float* b1  = (const float*)d_in[4];
    const float* W2  = (const float*)d_in[5];
    const float* b2  = (const float*)d_in[6];
    const float* pW1 = (const float*)d_in[7];
    const float* pb1 = (const float*)d_in[8];
    const float* pW2 = (const float*)d_in[9];
    const float* pb2 = (const float*)d_in[10];
    const float* pW3 = (const float*)d_in[11];
    const float* pb3 = (const float*)d_in[12];
    float* out = (float*)d_out;

    int N = in_sizes[0] / 5;
    int E = in_sizes[1] / 2;
    const int TB = 256;
    int nb = (N + TB - 1) / TB;
    int eb = (E + TB - 1) / TB;

    k_zero<<<nb, TB>>>(N);
    k_deg<<<eb, TB>>>(ei, (const float4*)ea, E);
    k_dis<<<nb, TB>>>(x, N);
    k_agg1<<<eb, TB>>>(ei, E);
    k_post<<<nb, TB>>>(W1, b1, W2, b2, pW1, pb1, pW2, pb2, pW3, pb3, out, N);
}

// round 7
// speedup vs baseline: 1.2101x; 1.1633x over previous
#include <cuda_runtime.h>
#include <cuda_fp16.h>
#include <math.h>

#define N_NODES_MAX 100000
#define N_EDGES_MAX 3200000

// Scratch (device globals; zero-initialized at module load, and every launch
// restores the all-zero invariant for deg/w2/aggh/acc/done before it returns).
__device__ __align__(128) float  g_deg[N_NODES_MAX];       // deg accum, then dis (in place)
__device__ __align__(128) float  g_w2[N_NODES_MAX];        // sum over out-edges of ewc*dis[dst]
__device__ __align__(128) float4 g_xs[N_NODES_MAX * 2];    // x*dis fp32, padded to 32B/node
__device__ __align__(128) uint4  g_aggh[N_NODES_MAX];      // 5-dim fp16 accumulator, 16B/node
__device__ __align__(128) float  g_ewc[N_EDGES_MAX];       // compact edge weight
__device__ float g_acc[16];                                // final 16-vec reduction
__device__ unsigned int g_done;                            // k_post completion counter

__device__ __forceinline__ void red_h8(uint4* p, unsigned a, unsigned b, unsigned c, unsigned d) {
    asm volatile("red.global.add.noftz.v4.f16x2 [%0], {%1,%2,%3,%4};"
                 :: "l"(p), "r"(a), "r"(b), "r"(c), "r"(d) : "memory");
}
__device__ __forceinline__ void red1(float* p, float a) {
    asm volatile("red.global.add.f32 [%0], %1;" :: "l"(p), "f"(a) : "memory");
}

// ---------------------------------------------------------------------------
// Pass 1: deg[dst] += ew; compact edge weights (deg starts at zero invariant)
// ---------------------------------------------------------------------------
__global__ void k_deg(const int* __restrict__ ei, const float4* __restrict__ ea4, int E) {
    int e = blockIdx.x * blockDim.x + threadIdx.x;
    if (e >= E) return;
    int d = ei[E + e];
    float w = ea4[e].x;
    g_ewc[e] = w;
    red1(&g_deg[d], w);
}

// ---------------------------------------------------------------------------
// Pass 2: dis = rsqrt(1 + deg); xs = x * dis (padded to 8 floats)
// ---------------------------------------------------------------------------
__global__ void k_dis(const float* __restrict__ x, int N) {
    int i = blockIdx.x * blockDim.x + threadIdx.x;
    if (i >= N) return;
    float di = rsqrtf(1.0f + g_deg[i]);
    g_deg[i] = di;
    float x0 = x[i * 5 + 0], x1 = x[i * 5 + 1], x2 = x[i * 5 + 2];
    float x3 = x[i * 5 + 3], x4 = x[i * 5 + 4];
    g_xs[i * 2]     = make_float4(x0 * di, x1 * di, x2 * di, x3 * di);
    g_xs[i * 2 + 1] = make_float4(x4 * di, 0.f, 0.f, 0.f);
}

// ---------------------------------------------------------------------------
// Pass 3: per edge: c = ewc * dis[dst]
//   aggh[dst] += half(xs[src] * c)   (ONE 16B f16x2 vector red)
//   w2[src]   += c                   (fp32 red)
// ---------------------------------------------------------------------------
__global__ void k_agg1(const int* __restrict__ ei, int E) {
    int e = blockIdx.x * blockDim.x + threadIdx.x;
    if (e >= E) return;
    int s = ei[e];
    int d = ei[E + e];
    float c = g_ewc[e] * g_deg[d];
    float4 m0 = g_xs[(size_t)s * 2];
    float  m4 = ((const float*)&g_xs[(size_t)s * 2 + 1])[0];
    __half2 p0 = __floats2half2_rn(m0.x * c, m0.y * c);
    __half2 p1 = __floats2half2_rn(m0.z * c, m0.w * c);
    __half2 p2 = __floats2half2_rn(m4 * c, 0.f);
    red_h8(&g_aggh[d], *(unsigned*)&p0, *(unsigned*)&p1, *(unsigned*)&p2, 0u);
    red1(&g_w2[s], c);
}

// ---------------------------------------------------------------------------
// Pass 4 (fused): per node:
//   a5 = float(aggh) + xs*dis (self loop);  h = relu(a5 @ W1 + b1)  (5 -> 16)
//   acc += h * (dis*w2 + dis^2)
//   restore zero-invariant: aggh=0, w2=0, deg=0
// Last block: state = (acc/N)@W2 + b2; MLP 4->128->64->50; softmax; acc=0
// ---------------------------------------------------------------------------
__global__ void k_post(const float* __restrict__ W1, const float* __restrict__ b1,
                       const float* __restrict__ W2, const float* __restrict__ b2,
                       const float* __restrict__ pW1, const float* __restrict__ pb1,
                       const float* __restrict__ pW2, const float* __restrict__ pb2,
                       const float* __restrict__ pW3, const float* __restrict__ pb3,
                       float* __restrict__ out, int N) {
    __shared__ float sW[80];
    __shared__ float sB[16];
    if (threadIdx.x < 80) sW[threadIdx.x] = W1[threadIdx.x];
    if (threadIdx.x < 16) sB[threadIdx.x] = b1[threadIdx.x];
    __syncthreads();
    int i = blockIdx.x * blockDim.x + threadIdx.x;
    float v[16];
#pragma unroll
    for (int c = 0; c < 16; c++) v[c] = 0.f;
    if (i < N) {
        float di = g_deg[i];
        float coef = fmaf(di, g_w2[i], di * di);
        uint4 ah = g_aggh[i];
        float4 xs = g_xs[i * 2];
        float  x4 = ((const float*)&g_xs[i * 2 + 1])[0];
        // restore zero-invariant for next launch
        g_aggh[i] = make_uint4(0u, 0u, 0u, 0u);
        g_w2[i] = 0.f;
        g_deg[i] = 0.f;
        float2 f01 = __half22float2(*(__half2*)&ah.x);
        float2 f23 = __half22float2(*(__half2*)&ah.y);
        float2 f4_ = __half22float2(*(__half2*)&ah.z);
        float a5[5];
        a5[0] = fmaf(xs.x, di, f01.x);
        a5[1] = fmaf(xs.y, di, f01.y);
        a5[2] = fmaf(xs.z, di, f23.x);
        a5[3] = fmaf(xs.w, di, f23.y);
        a5[4] = fmaf(x4,   di, f4_.x);
#pragma unroll
        for (int c = 0; c < 16; c++) {
            float h = sB[c];
#pragma unroll
            for (int k = 0; k < 5; k++) h = fmaf(a5[k], sW[k * 16 + c], h);
            v[c] = fmaxf(h, 0.f) * coef;
        }
    }
    // warp -> block -> global reduction
#pragma unroll
    for (int c = 0; c < 16; c++)
#pragma unroll
        for (int m = 16; m > 0; m >>= 1) v[c] += __shfl_xor_sync(0xffffffffu, v[c], m);
    __shared__ float sb[16];
    if (threadIdx.x < 16) sb[threadIdx.x] = 0.f;
    __syncthreads();
    if ((threadIdx.x & 31) == 0) {
#pragma unroll
        for (int c = 0; c < 16; c++) atomicAdd(&sb[c], v[c]);
    }
    __syncthreads();
    if (threadIdx.x < 16) atomicAdd(&g_acc[threadIdx.x], sb[threadIdx.x]);

    // ---- last-block-done: run the tiny MLP head ----
    __shared__ bool isLast;
    __threadfence();
    if (threadIdx.x == 0) {
        unsigned int ticket = atomicAdd(&g_done, 1u);
        isLast = (ticket == gridDim.x - 1);
    }
    __syncthreads();
    if (!isLast) return;
    if (threadIdx.x == 0) g_done = 0u;   // reset for next launch

    __shared__ float st[4];
    __shared__ float z1[128];
    __shared__ float z2[64];
    __shared__ float lg[50];
    __shared__ float ms[2];
    int t = threadIdx.x;
    if (t < 4) {
        float s = 0.f;
#pragma unroll
        for (int k = 0; k < 16; k++) {
            float av;
            asm volatile("ld.volatile.global.f32 %0, [%1];" : "=f"(av) : "l"(&g_acc[k]));
            s = fmaf(av, W2[k * 4 + t], s);
        }
        st[t] = s / (float)N + b2[t];
    }
    __syncthreads();
    if (t < 16) g_acc[t] = 0.f;          // restore zero-invariant
    if (t < 128) {
        float vv = pb1[t];
#pragma unroll
        for (int j = 0; j < 4; j++) vv = fmaf(st[j], pW1[j * 128 + t], vv);
        z1[t] = fmaxf(vv, 0.f);
    }
    __syncthreads();
    if (t < 64) {
        float vv = pb2[t];
#pragma unroll 8
        for (int k = 0; k < 128; k++) vv = fmaf(z1[k], pW2[k * 64 + t], vv);
        z2[t] = fmaxf(vv, 0.f);
    }
    __syncthreads();
    if (t < 50) {
        float vv = pb3[t];
#pragma unroll 8
        for (int k = 0; k < 64; k++) vv = fmaf(z2[k], pW3[k * 50 + t], vv);
        lg[t] = vv;
    }
    __syncthreads();
    if (t == 0) {
        float m = lg[0];
        for (int k = 1; k < 50; k++) m = fmaxf(m, lg[k]);
        float s = 0.f;
        for (int k = 0; k < 50; k++) s += expf(lg[k] - m);
        ms[0] = m;
        ms[1] = s;
    }
    __syncthreads();
    if (t < 50) out[t] = expf(lg[t] - ms[0]) / ms[1];
}

// ---------------------------------------------------------------------------
extern "C" void kernel_launch(void* const* d_in, const int* in_sizes, int n_in,
                              void* d_out, int out_size) {
    const float* x   = (const float*)d_in[0];
    const int*   ei  = (const int*)  d_in[1];
    const float* ea  = (const float*)d_in[2];
    const float* W1  = (const float*)d_in[3];
    const float* b1  = (const float*)d_in[4];
    const float* W2  = (const float*)d_in[5];
    const float* b2  = (const float*)d_in[6];
    const float* pW1 = (const float*)d_in[7];
    const float* pb1 = (const float*)d_in[8];
    const float* pW2 = (const float*)d_in[9];
    const float* pb2 = (const float*)d_in[10];
    const float* pW3 = (const float*)d_in[11];
    const float* pb3 = (const float*)d_in[12];
    float* out = (float*)d_out;

    int N = in_sizes[0] / 5;
    int E = in_sizes[1] / 2;
    const int TB = 256;
    int nb = (N + TB - 1) / TB;
    int eb = (E + TB - 1) / TB;

    k_deg<<<eb, TB>>>(ei, (const float4*)ea, E);
    k_dis<<<nb, TB>>>(x, N);
    k_agg1<<<eb, TB>>>(ei, E);
    k_post<<<nb, TB>>>(W1, b1, W2, b2, pW1, pb1, pW2, pb2, pW3, pb3, out, N);
}